// round 11
// baseline (speedup 1.0000x reference)
#include <cuda_runtime.h>
#include <cuda_bf16.h>
#include <cstdint>

// Problem constants (match reference)
#define BATCH      4
#define SEQ_LEN    8192
#define EMBED_DIM  512
#define NBUCKETS   500000
#define HASH_MASK  0x7FFFFFu   // 2^23 - 1
#define HASH_BASE  260u        // VOCAB + 1
#define MAX_N      8

#define NPOS       (BATCH * SEQ_LEN)   // 32768
#define GRID_CTAS  1776                // 148 SMs x 12 CTAs: one full residency set

// Persistent grid-stride kernel: 1776 CTAs loop over positions, dissolving
// wave quantization (32768 one-shot CTAs = 18.45 waves -> ~2us partial-wave
// idle). No smem / no barrier: each thread loads its own 8 tokens (same
// addresses warp-wide -> 1 broadcast wavefront, L1-hot across iterations).
__global__ __launch_bounds__(128, 12)
void hash_ngram_kernel(const int* __restrict__ tokens,
                       const float* __restrict__ main_w,
                       const float* __restrict__ shared_w,
                       const float* __restrict__ size_w,
                       float* __restrict__ out)
{
    const int d4 = threadIdx.x;  // float4 lane, 0..127 (512/4), fixed per thread
    const float4* __restrict__ g4 = (const float4*)shared_w;
    const float4* __restrict__ m4 = (const float4*)main_w;
    const float4* __restrict__ z4 = (const float4*)size_w;

    for (int pos = blockIdx.x; pos < NPOS; pos += GRID_CTAS) {
        const int b = pos >> 13;            // / SEQ_LEN
        const int s = pos & (SEQ_LEN - 1);  // % SEQ_LEN
        const int base = b * SEQ_LEN + s;

        // Hash chain over the 8 trailing tokens. Token loads are warp-uniform
        // (broadcast) and L1-resident (consecutive positions reuse 7 of 8).
        int sidx[MAX_N - 2];
        int tok0;
        {
            unsigned P   = 1u;   // 260^j mod 2^23
            unsigned acc = 0u;   // running sum of masked terms
            #pragma unroll
            for (int j = 0; j < MAX_N; ++j) {
                const int t = (s - j >= 0) ? __ldg(&tokens[base - j]) : 0;
                if (j == 0) tok0 = t;
                acc += ((unsigned)t * P) & HASH_MASK;    // t[s-j]*260^j mod 2^23
                P = (P * HASH_BASE) & HASH_MASK;
                const int n = j + 1;                     // n-gram length
                if (n >= 3) {
                    const unsigned h = acc & HASH_MASK;  // sum mod 2^23
                    sidx[n - 3] = (s >= n - 1) ? (int)(h % NBUCKETS) : 0;
                }
            }
        }

        // Cached contributions first (main_w row: L2-resident; size_w: 12KB,
        // L1-resident) — accumulated immediately, registers die before the
        // gather batch needs headroom.
        float4 vm = __ldg(&m4[(size_t)tok0 * 128 + d4]);
        float ax = vm.x, ay = vm.y, az = vm.z, aw = vm.w;
        #pragma unroll
        for (int r = 0; r < MAX_N - 2; ++r) {
            const float4 vz = __ldg(&z4[(size_t)r * 128 + d4]);
            ax += vz.x; ay += vz.y; az += vz.z; aw += vz.w;
        }

        // The 6 DRAM gathers, batched for MLP.
        float4 vg[MAX_N - 2];
        #pragma unroll
        for (int r = 0; r < MAX_N - 2; ++r)
            vg[r] = __ldg(&g4[(size_t)sidx[r] * 128 + d4]);

        #pragma unroll
        for (int r = 0; r < MAX_N - 2; ++r) {
            ax += vg[r].x;
            ay += vg[r].y;
            az += vg[r].z;
            aw += vg[r].w;
        }

        const float inv = 1.0f / 7.0f;   // 1 + (MAX_N - 2) contributors
        float4 o;
        o.x = ax * inv; o.y = ay * inv; o.z = az * inv; o.w = aw * inv;
        // Streaming store: keep the 64MB output from evicting gather lines.
        __stcs(&((float4*)out)[(size_t)pos * 128 + d4], o);
    }
}

extern "C" void kernel_launch(void* const* d_in, const int* in_sizes, int n_in,
                              void* d_out, int out_size)
{
    const int*   tokens   = (const int*)  d_in[0];   // [4, 8192] int32
    const float* main_w   = (const float*)d_in[1];   // [259, 512] f32
    const float* shared_w = (const float*)d_in[2];   // [500000, 512] f32
    const float* size_w   = (const float*)d_in[3];   // [6, 512] f32
    float*       out      = (float*)d_out;           // [4, 8192, 512] f32

    (void)in_sizes; (void)n_in; (void)out_size;

    hash_ngram_kernel<<<GRID_CTAS, 128>>>(tokens, main_w, shared_w, size_w, out);
}

// round 12
// speedup vs baseline: 1.0292x; 1.0292x over previous
#include <cuda_runtime.h>
#include <cuda_bf16.h>
#include <cstdint>

// Problem constants (match reference)
#define BATCH      4
#define SEQ_LEN    8192
#define EMBED_DIM  512
#define NBUCKETS   500000
#define HASH_MASK  0x7FFFFFu   // 2^23 - 1
#define HASH_BASE  260u        // VOCAB + 1
#define MAX_N      8

// One-shot CTA per (b, s) position (hardware CTA scheduler supplies
// inter-position MLP — the persistent-loop variant serialized gather
// batches and lost 4us). 128 threads, one float4 lane each.
// No smem / no barrier: each thread loads its own 8 tokens (warp-uniform
// broadcast, L1-hot: 128KB token array, neighboring CTAs share 7/8 tokens).
// This removes the BAR.SYNC behind an L2-latency token load from the
// critical path of every one of 32768 CTAs, and decouples the 4 warps.
// __launch_bounds__(128,12) = hard 42-reg budget (keeps the size_w loads
// from being batched into the gather cluster; proven 40-reg schedule).
__global__ __launch_bounds__(128, 12)
void hash_ngram_kernel(const int* __restrict__ tokens,
                       const float* __restrict__ main_w,
                       const float* __restrict__ shared_w,
                       const float* __restrict__ size_w,
                       float* __restrict__ out)
{
    const int pos = blockIdx.x;           // 0 .. BATCH*SEQ_LEN-1
    const int b   = pos >> 13;            // / SEQ_LEN
    const int s   = pos & (SEQ_LEN - 1);  // % SEQ_LEN
    const int base = b * SEQ_LEN + s;

    // Hash chain over the 8 trailing tokens (redundant per thread, pure
    // ALU + broadcast loads — no staging, no barrier).
    int sidx[MAX_N - 2];
    int tok0;
    {
        unsigned P   = 1u;   // 260^j mod 2^23
        unsigned acc = 0u;   // running sum of masked terms
        #pragma unroll
        for (int j = 0; j < MAX_N; ++j) {
            const int t = (s - j >= 0) ? __ldg(&tokens[base - j]) : 0;
            if (j == 0) tok0 = t;
            acc += ((unsigned)t * P) & HASH_MASK;    // t[s-j]*260^j mod 2^23
            P = (P * HASH_BASE) & HASH_MASK;
            const int n = j + 1;                     // n-gram length
            if (n >= 3) {
                const unsigned h = acc & HASH_MASK;  // sum mod 2^23
                sidx[n - 3] = (s >= n - 1) ? (int)(h % NBUCKETS) : 0;
            }
        }
    }

    const int d4 = threadIdx.x;  // float4 lane, 0..127 (512/4)
    const float4* __restrict__ g4 = (const float4*)shared_w;
    const float4* __restrict__ m4 = (const float4*)main_w;
    const float4* __restrict__ z4 = (const float4*)size_w;

    // Cached contributions first (main_w row: L2-resident; size_w: 12KB,
    // L1-resident) — accumulated immediately, registers die before the
    // gather batch needs headroom.
    float4 vm = __ldg(&m4[(size_t)tok0 * 128 + d4]);
    float ax = vm.x, ay = vm.y, az = vm.z, aw = vm.w;
    #pragma unroll
    for (int r = 0; r < MAX_N - 2; ++r) {
        const float4 vz = __ldg(&z4[(size_t)r * 128 + d4]);
        ax += vz.x; ay += vz.y; az += vz.z; aw += vz.w;
    }

    // The 6 DRAM gathers, batched for MLP.
    float4 vg[MAX_N - 2];
    #pragma unroll
    for (int r = 0; r < MAX_N - 2; ++r)
        vg[r] = __ldg(&g4[(size_t)sidx[r] * 128 + d4]);

    #pragma unroll
    for (int r = 0; r < MAX_N - 2; ++r) {
        ax += vg[r].x;
        ay += vg[r].y;
        az += vg[r].z;
        aw += vg[r].w;
    }

    const float inv = 1.0f / 7.0f;   // 1 + (MAX_N - 2) contributors
    float4 o;
    o.x = ax * inv; o.y = ay * inv; o.z = az * inv; o.w = aw * inv;
    // Streaming store: keep the 64MB output from evicting gather lines.
    __stcs(&((float4*)out)[(size_t)pos * 128 + d4], o);
}

extern "C" void kernel_launch(void* const* d_in, const int* in_sizes, int n_in,
                              void* d_out, int out_size)
{
    const int*   tokens   = (const int*)  d_in[0];   // [4, 8192] int32
    const float* main_w   = (const float*)d_in[1];   // [259, 512] f32
    const float* shared_w = (const float*)d_in[2];   // [500000, 512] f32
    const float* size_w   = (const float*)d_in[3];   // [6, 512] f32
    float*       out      = (float*)d_out;           // [4, 8192, 512] f32

    (void)in_sizes; (void)n_in; (void)out_size;

    hash_ngram_kernel<<<BATCH * SEQ_LEN, 128>>>(tokens, main_w, shared_w, size_w, out);
}

// round 13
// speedup vs baseline: 1.0335x; 1.0041x over previous
#include <cuda_runtime.h>
#include <cuda_bf16.h>
#include <cstdint>

// Problem constants (match reference)
#define BATCH      4
#define SEQ_LEN    8192
#define EMBED_DIM  512
#define NBUCKETS   500000
#define HASH_MASK  0x7FFFFFu   // 2^23 - 1
#define HASH_BASE  260u        // VOCAB + 1
#define MAX_N      8
#define NPOS       (BATCH * SEQ_LEN)   // 32768

// Two adjacent positions per CTA: doubles per-warp gather MLP (12 batched
// LDG.128 in flight vs 6), which the 3-term LDG model says is the lever on
// random-gather DRAM efficiency. The pair (2k, 2k+1) never crosses a batch
// boundary (SEQ_LEN even), shares 8/9 trailing tokens, and has an identical
// size_w sum (folded once). Barrier-free: all loads warp-uniform or lane-
// private; no smem. __launch_bounds__(128,8) = 64-reg budget.
__global__ __launch_bounds__(128, 8)
void hash_ngram_kernel(const int* __restrict__ tokens,
                       const float* __restrict__ main_w,
                       const float* __restrict__ shared_w,
                       const float* __restrict__ size_w,
                       float* __restrict__ out)
{
    const int pos0 = blockIdx.x * 2;       // even position of the pair
    const int b    = pos0 >> 13;           // / SEQ_LEN (same for both)
    const int s0   = pos0 & (SEQ_LEN - 1); // % SEQ_LEN
    const int s1   = s0 + 1;
    const int base = b * SEQ_LEN;

    // 9 trailing tokens cover both hash chains: t[s1], t[s0], t[s0-1]...t[s0-7].
    int tk[MAX_N + 1];   // tk[j] = t[s1 - j], j = 0..8
    #pragma unroll
    for (int j = 0; j <= MAX_N; ++j)
        tk[j] = (s1 - j >= 0) ? __ldg(&tokens[base + s1 - j]) : 0;

    // Hash chains (redundant per thread, pure ALU).
    int sidxA[MAX_N - 2];   // position s0: tokens tk[1..8]
    int sidxB[MAX_N - 2];   // position s1: tokens tk[0..7]
    {
        unsigned P = 1u, accA = 0u, accB = 0u;
        #pragma unroll
        for (int j = 0; j < MAX_N; ++j) {
            accA += ((unsigned)tk[j + 1] * P) & HASH_MASK;
            accB += ((unsigned)tk[j]     * P) & HASH_MASK;
            P = (P * HASH_BASE) & HASH_MASK;
            const int n = j + 1;
            if (n >= 3) {
                sidxA[n - 3] = (s0 >= n - 1) ? (int)((accA & HASH_MASK) % NBUCKETS) : 0;
                sidxB[n - 3] = (s1 >= n - 1) ? (int)((accB & HASH_MASK) % NBUCKETS) : 0;
            }
        }
    }

    const int d4 = threadIdx.x;  // float4 lane, 0..127 (512/4)
    const float4* __restrict__ g4 = (const float4*)shared_w;
    const float4* __restrict__ m4 = (const float4*)main_w;
    const float4* __restrict__ z4 = (const float4*)size_w;

    // Shared cached contribution: size_w sum is identical for both positions.
    float zx, zy, zz, zw;
    {
        float4 v = __ldg(&z4[d4]);
        zx = v.x; zy = v.y; zz = v.z; zw = v.w;
        #pragma unroll
        for (int r = 1; r < MAX_N - 2; ++r) {
            v = __ldg(&z4[(size_t)r * 128 + d4]);
            zx += v.x; zy += v.y; zz += v.z; zw += v.w;
        }
    }

    // Main rows (L2-resident) seed the two accumulators.
    float4 vmA = __ldg(&m4[(size_t)tk[1] * 128 + d4]);
    float4 vmB = __ldg(&m4[(size_t)tk[0] * 128 + d4]);
    float axA = vmA.x + zx, ayA = vmA.y + zy, azA = vmA.z + zz, awA = vmA.w + zw;
    float axB = vmB.x + zx, ayB = vmB.y + zy, azB = vmB.z + zz, awB = vmB.w + zw;

    // 12 DRAM gathers, all batched before any consumption — max MLP.
    float4 vgA[MAX_N - 2], vgB[MAX_N - 2];
    #pragma unroll
    for (int r = 0; r < MAX_N - 2; ++r)
        vgA[r] = __ldg(&g4[(size_t)sidxA[r] * 128 + d4]);
    #pragma unroll
    for (int r = 0; r < MAX_N - 2; ++r)
        vgB[r] = __ldg(&g4[(size_t)sidxB[r] * 128 + d4]);

    #pragma unroll
    for (int r = 0; r < MAX_N - 2; ++r) {
        axA += vgA[r].x; ayA += vgA[r].y; azA += vgA[r].z; awA += vgA[r].w;
    }
    #pragma unroll
    for (int r = 0; r < MAX_N - 2; ++r) {
        axB += vgB[r].x; ayB += vgB[r].y; azB += vgB[r].z; awB += vgB[r].w;
    }

    const float inv = 1.0f / 7.0f;   // 1 + (MAX_N - 2) contributors
    float4 oA, oB;
    oA.x = axA * inv; oA.y = ayA * inv; oA.z = azA * inv; oA.w = awA * inv;
    oB.x = axB * inv; oB.y = ayB * inv; oB.z = azB * inv; oB.w = awB * inv;

    float4* o4 = (float4*)out;
    __stcs(&o4[(size_t)pos0 * 128 + d4], oA);
    __stcs(&o4[(size_t)(pos0 + 1) * 128 + d4], oB);
}

extern "C" void kernel_launch(void* const* d_in, const int* in_sizes, int n_in,
                              void* d_out, int out_size)
{
    const int*   tokens   = (const int*)  d_in[0];   // [4, 8192] int32
    const float* main_w   = (const float*)d_in[1];   // [259, 512] f32
    const float* shared_w = (const float*)d_in[2];   // [500000, 512] f32
    const float* size_w   = (const float*)d_in[3];   // [6, 512] f32
    float*       out      = (float*)d_out;           // [4, 8192, 512] f32

    (void)in_sizes; (void)n_in; (void)out_size;

    hash_ngram_kernel<<<NPOS / 2, 128>>>(tokens, main_w, shared_w, size_w, out);
}

// round 14
// speedup vs baseline: 1.0349x; 1.0014x over previous
#include <cuda_runtime.h>
#include <cuda_bf16.h>
#include <cstdint>

// Problem constants (match reference)
#define BATCH      4
#define SEQ_LEN    8192
#define EMBED_DIM  512
#define NBUCKETS   500000
#define HASH_MASK  0x7FFFFFu   // 2^23 - 1
#define HASH_BASE  260u        // VOCAB + 1
#define MAX_N      8
#define NPOS       (BATCH * SEQ_LEN)   // 32768

// Two adjacent positions per CTA, 12 DRAM gathers batched per thread.
// R13 delta vs R12: gathers are issued IMMEDIATELY after the hash; the
// ~10 cached loads (size_w sum + 2 main rows) execute while the gathers
// are in flight, hiding their L1/L2 latency under the DRAM flight instead
// of serializing in front of it. Peak live regs ~60-64, within the
// __launch_bounds__(128,8) 64-reg budget (watch for spills in ncu).
__global__ __launch_bounds__(128, 8)
void hash_ngram_kernel(const int* __restrict__ tokens,
                       const float* __restrict__ main_w,
                       const float* __restrict__ shared_w,
                       const float* __restrict__ size_w,
                       float* __restrict__ out)
{
    const int pos0 = blockIdx.x * 2;       // even position of the pair
    const int b    = pos0 >> 13;           // / SEQ_LEN (same for both)
    const int s0   = pos0 & (SEQ_LEN - 1); // % SEQ_LEN
    const int s1   = s0 + 1;
    const int base = b * SEQ_LEN;

    // 9 trailing tokens cover both hash chains: t[s1], t[s0], ... t[s0-7].
    int tk[MAX_N + 1];   // tk[j] = t[s1 - j], j = 0..8
    #pragma unroll
    for (int j = 0; j <= MAX_N; ++j)
        tk[j] = (s1 - j >= 0) ? __ldg(&tokens[base + s1 - j]) : 0;

    // Hash chains (redundant per thread, pure ALU).
    int sidxA[MAX_N - 2];   // position s0: tokens tk[1..8]
    int sidxB[MAX_N - 2];   // position s1: tokens tk[0..7]
    {
        unsigned P = 1u, accA = 0u, accB = 0u;
        #pragma unroll
        for (int j = 0; j < MAX_N; ++j) {
            accA += ((unsigned)tk[j + 1] * P) & HASH_MASK;
            accB += ((unsigned)tk[j]     * P) & HASH_MASK;
            P = (P * HASH_BASE) & HASH_MASK;
            const int n = j + 1;
            if (n >= 3) {
                sidxA[n - 3] = (s0 >= n - 1) ? (int)((accA & HASH_MASK) % NBUCKETS) : 0;
                sidxB[n - 3] = (s1 >= n - 1) ? (int)((accB & HASH_MASK) % NBUCKETS) : 0;
            }
        }
    }

    const int d4 = threadIdx.x;  // float4 lane, 0..127 (512/4)
    const float4* __restrict__ g4 = (const float4*)shared_w;
    const float4* __restrict__ m4 = (const float4*)main_w;
    const float4* __restrict__ z4 = (const float4*)size_w;

    // 12 DRAM gathers FIRST — start the long-latency flight immediately.
    float4 vgA[MAX_N - 2], vgB[MAX_N - 2];
    #pragma unroll
    for (int r = 0; r < MAX_N - 2; ++r)
        vgA[r] = __ldg(&g4[(size_t)sidxA[r] * 128 + d4]);
    #pragma unroll
    for (int r = 0; r < MAX_N - 2; ++r)
        vgB[r] = __ldg(&g4[(size_t)sidxB[r] * 128 + d4]);

    // Cached work under the DRAM flight: shared size_w sum (identical for
    // both positions) and the two L2-resident main rows.
    float zx, zy, zz, zw;
    {
        float4 v = __ldg(&z4[d4]);
        zx = v.x; zy = v.y; zz = v.z; zw = v.w;
        #pragma unroll
        for (int r = 1; r < MAX_N - 2; ++r) {
            v = __ldg(&z4[(size_t)r * 128 + d4]);
            zx += v.x; zy += v.y; zz += v.z; zw += v.w;
        }
    }
    float4 vmA = __ldg(&m4[(size_t)tk[1] * 128 + d4]);
    float4 vmB = __ldg(&m4[(size_t)tk[0] * 128 + d4]);
    float axA = vmA.x + zx, ayA = vmA.y + zy, azA = vmA.z + zz, awA = vmA.w + zw;
    float axB = vmB.x + zx, ayB = vmB.y + zy, azB = vmB.z + zz, awB = vmB.w + zw;

    // Consume the gathers.
    #pragma unroll
    for (int r = 0; r < MAX_N - 2; ++r) {
        axA += vgA[r].x; ayA += vgA[r].y; azA += vgA[r].z; awA += vgA[r].w;
    }
    #pragma unroll
    for (int r = 0; r < MAX_N - 2; ++r) {
        axB += vgB[r].x; ayB += vgB[r].y; azB += vgB[r].z; awB += vgB[r].w;
    }

    const float inv = 1.0f / 7.0f;   // 1 + (MAX_N - 2) contributors
    float4 oA, oB;
    oA.x = axA * inv; oA.y = ayA * inv; oA.z = azA * inv; oA.w = awA * inv;
    oB.x = axB * inv; oB.y = ayB * inv; oB.z = azB * inv; oB.w = awB * inv;

    float4* o4 = (float4*)out;
    __stcs(&o4[(size_t)pos0 * 128 + d4], oA);
    __stcs(&o4[(size_t)(pos0 + 1) * 128 + d4], oB);
}

extern "C" void kernel_launch(void* const* d_in, const int* in_sizes, int n_in,
                              void* d_out, int out_size)
{
    const int*   tokens   = (const int*)  d_in[0];   // [4, 8192] int32
    const float* main_w   = (const float*)d_in[1];   // [259, 512] f32
    const float* shared_w = (const float*)d_in[2];   // [500000, 512] f32
    const float* size_w   = (const float*)d_in[3];   // [6, 512] f32
    float*       out      = (float*)d_out;           // [4, 8192, 512] f32

    (void)in_sizes; (void)n_in; (void)out_size;

    hash_ngram_kernel<<<NPOS / 2, 128>>>(tokens, main_w, shared_w, size_w, out);
}

// round 15
// speedup vs baseline: 1.0358x; 1.0009x over previous
#include <cuda_runtime.h>
#include <cuda_bf16.h>
#include <cstdint>

// Problem constants (match reference)
#define BATCH      4
#define SEQ_LEN    8192
#define EMBED_DIM  512
#define NBUCKETS   500000
#define HASH_MASK  0x7FFFFFu   // 2^23 - 1
#define HASH_BASE  260u        // VOCAB + 1
#define MAX_N      8
#define NPOS       (BATCH * SEQ_LEN)   // 32768

// 256-bit (v8.b32) global loads — sm_10x only. Halves gather LDG count at
// identical bytes/thread; the direct L2::evict_last modifier is legal (and
// register-free) on this width.
struct F8 { float v[8]; };

__device__ __forceinline__ F8 ldg256_el(const float* p)
{
    unsigned u0,u1,u2,u3,u4,u5,u6,u7;
    asm("ld.global.nc.L2::evict_last.v8.b32 {%0,%1,%2,%3,%4,%5,%6,%7}, [%8];"
        : "=r"(u0),"=r"(u1),"=r"(u2),"=r"(u3),
          "=r"(u4),"=r"(u5),"=r"(u6),"=r"(u7)
        : "l"(p));
    F8 r;
    r.v[0]=__uint_as_float(u0); r.v[1]=__uint_as_float(u1);
    r.v[2]=__uint_as_float(u2); r.v[3]=__uint_as_float(u3);
    r.v[4]=__uint_as_float(u4); r.v[5]=__uint_as_float(u5);
    r.v[6]=__uint_as_float(u6); r.v[7]=__uint_as_float(u7);
    return r;
}

__device__ __forceinline__ F8 ldg256(const float* p)
{
    unsigned u0,u1,u2,u3,u4,u5,u6,u7;
    asm("ld.global.nc.v8.b32 {%0,%1,%2,%3,%4,%5,%6,%7}, [%8];"
        : "=r"(u0),"=r"(u1),"=r"(u2),"=r"(u3),
          "=r"(u4),"=r"(u5),"=r"(u6),"=r"(u7)
        : "l"(p));
    F8 r;
    r.v[0]=__uint_as_float(u0); r.v[1]=__uint_as_float(u1);
    r.v[2]=__uint_as_float(u2); r.v[3]=__uint_as_float(u3);
    r.v[4]=__uint_as_float(u4); r.v[5]=__uint_as_float(u5);
    r.v[6]=__uint_as_float(u6); r.v[7]=__uint_as_float(u7);
    return r;
}

// One CTA = 128 threads = 2 adjacent positions; 64 threads per position,
// each owning a 32B (8-float) lane of the 512-dim embedding. Per-thread:
// 6 gather LDG.256 (same in-flight bytes as 12 LDG.128, half the
// instructions / L1tex tag work). pos is warp-uniform (warps 0-1 -> pos0,
// warps 2-3 -> pos1) so all control flow & token loads stay convergent.
// Barrier-free, smem-free. __launch_bounds__(128,8) = 64-reg budget.
__global__ __launch_bounds__(128, 8)
void hash_ngram_kernel(const int* __restrict__ tokens,
                       const float* __restrict__ main_w,
                       const float* __restrict__ shared_w,
                       const float* __restrict__ size_w,
                       float* __restrict__ out)
{
    const int pos  = blockIdx.x * 2 + (threadIdx.x >> 6);  // warp-uniform
    const int d8   = threadIdx.x & 63;                     // 32B lane
    const int b    = pos >> 13;            // / SEQ_LEN
    const int s    = pos & (SEQ_LEN - 1);  // % SEQ_LEN
    const int base = b * SEQ_LEN + s;

    // Hash chain over the 8 trailing tokens (redundant per thread; token
    // loads are warp-uniform broadcasts, L1-hot).
    int sidx[MAX_N - 2];
    int tok0;
    {
        unsigned P   = 1u;   // 260^j mod 2^23
        unsigned acc = 0u;   // running sum of masked terms
        #pragma unroll
        for (int j = 0; j < MAX_N; ++j) {
            const int t = (s - j >= 0) ? __ldg(&tokens[base - j]) : 0;
            if (j == 0) tok0 = t;
            acc += ((unsigned)t * P) & HASH_MASK;    // t[s-j]*260^j mod 2^23
            P = (P * HASH_BASE) & HASH_MASK;
            const int n = j + 1;                     // n-gram length
            if (n >= 3) {
                const unsigned h = acc & HASH_MASK;  // sum mod 2^23
                sidx[n - 3] = (s >= n - 1) ? (int)(h % NBUCKETS) : 0;
            }
        }
    }

    const int doff = d8 * 8;  // float offset within the 512-dim row

    // 6 DRAM gathers FIRST (256-bit each), batched for MLP.
    F8 vg[MAX_N - 2];
    #pragma unroll
    for (int r = 0; r < MAX_N - 2; ++r)
        vg[r] = ldg256_el(shared_w + (size_t)sidx[r] * EMBED_DIM + doff);

    // Cached work under the DRAM flight: main row (L2-resident) seeds the
    // accumulator, then the 6 L1-resident size_w rows fold in.
    float a[8];
    {
        F8 vm = ldg256(main_w + (size_t)tok0 * EMBED_DIM + doff);
        #pragma unroll
        for (int k = 0; k < 8; ++k) a[k] = vm.v[k];
        #pragma unroll
        for (int r = 0; r < MAX_N - 2; ++r) {
            F8 vz = ldg256(size_w + (size_t)r * EMBED_DIM + doff);
            #pragma unroll
            for (int k = 0; k < 8; ++k) a[k] += vz.v[k];
        }
    }

    // Consume the gathers.
    #pragma unroll
    for (int r = 0; r < MAX_N - 2; ++r)
        #pragma unroll
        for (int k = 0; k < 8; ++k) a[k] += vg[r].v[k];

    const float inv = 1.0f / 7.0f;   // 1 + (MAX_N - 2) contributors
    float4 o0, o1;
    o0.x = a[0]*inv; o0.y = a[1]*inv; o0.z = a[2]*inv; o0.w = a[3]*inv;
    o1.x = a[4]*inv; o1.y = a[5]*inv; o1.z = a[6]*inv; o1.w = a[7]*inv;

    // Streaming stores: keep the 64MB output from evicting gather lines.
    float4* o4 = (float4*)(out + (size_t)pos * EMBED_DIM + doff);
    __stcs(&o4[0], o0);
    __stcs(&o4[1], o1);
}

extern "C" void kernel_launch(void* const* d_in, const int* in_sizes, int n_in,
                              void* d_out, int out_size)
{
    const int*   tokens   = (const int*)  d_in[0];   // [4, 8192] int32
    const float* main_w   = (const float*)d_in[1];   // [259, 512] f32
    const float* shared_w = (const float*)d_in[2];   // [500000, 512] f32
    const float* size_w   = (const float*)d_in[3];   // [6, 512] f32
    float*       out      = (float*)d_out;           // [4, 8192, 512] f32

    (void)in_sizes; (void)n_in; (void)out_size;

    hash_ngram_kernel<<<NPOS / 2, 128>>>(tokens, main_w, shared_w, size_w, out);
}

// round 16
// speedup vs baseline: 1.0425x; 1.0065x over previous
#include <cuda_runtime.h>
#include <cuda_bf16.h>
#include <cstdint>

// Problem constants (match reference)
#define BATCH      4
#define SEQ_LEN    8192
#define EMBED_DIM  512
#define NBUCKETS   500000
#define HASH_MASK  0x7FFFFFu   // 2^23 - 1
#define HASH_BASE  260u        // VOCAB + 1
#define MAX_N      8
#define NPOS       (BATCH * SEQ_LEN)   // 32768

// 256-bit (v8.b32) global loads — sm_10x only. Halves gather LDG count at
// identical bytes/thread; the direct L2::evict_last modifier is legal (and
// register-free) on this width.
struct F8 { float v[8]; };

__device__ __forceinline__ F8 ldg256_el(const float* p)
{
    unsigned u0,u1,u2,u3,u4,u5,u6,u7;
    asm("ld.global.nc.L2::evict_last.v8.b32 {%0,%1,%2,%3,%4,%5,%6,%7}, [%8];"
        : "=r"(u0),"=r"(u1),"=r"(u2),"=r"(u3),
          "=r"(u4),"=r"(u5),"=r"(u6),"=r"(u7)
        : "l"(p));
    F8 r;
    r.v[0]=__uint_as_float(u0); r.v[1]=__uint_as_float(u1);
    r.v[2]=__uint_as_float(u2); r.v[3]=__uint_as_float(u3);
    r.v[4]=__uint_as_float(u4); r.v[5]=__uint_as_float(u5);
    r.v[6]=__uint_as_float(u6); r.v[7]=__uint_as_float(u7);
    return r;
}

__device__ __forceinline__ F8 ldg256(const float* p)
{
    unsigned u0,u1,u2,u3,u4,u5,u6,u7;
    asm("ld.global.nc.v8.b32 {%0,%1,%2,%3,%4,%5,%6,%7}, [%8];"
        : "=r"(u0),"=r"(u1),"=r"(u2),"=r"(u3),
          "=r"(u4),"=r"(u5),"=r"(u6),"=r"(u7)
        : "l"(p));
    F8 r;
    r.v[0]=__uint_as_float(u0); r.v[1]=__uint_as_float(u1);
    r.v[2]=__uint_as_float(u2); r.v[3]=__uint_as_float(u3);
    r.v[4]=__uint_as_float(u4); r.v[5]=__uint_as_float(u5);
    r.v[6]=__uint_as_float(u6); r.v[7]=__uint_as_float(u7);
    return r;
}

// One CTA = 128 threads = 2 adjacent positions; 64 threads per position,
// each owning a 32B (8-float) lane of the 512-dim embedding. Per-thread:
// 6 gather LDG.256 batched before any consumption (same in-flight bytes
// as 12 LDG.128, half the instructions / L1tex tag work). pos is
// warp-uniform (warps 0-1 -> pos0, warps 2-3 -> pos1) so all control flow
// & token loads stay convergent. Barrier-free, smem-free.
// __launch_bounds__(128,8) = 64-reg budget (measured 64 regs, no spills).
//
// Measured operating point (final): kernel ~68.1us, DRAM ~79.5% of 8TB/s,
// traffic within ~8% of compulsory — the random-gather HBM roofline.
// Levers tested & exhausted: occupancy (44-70%: neutral), per-warp MLP
// 6->12 (neutral), instruction count -50% (neutral), L2 policy (neutral),
// persistent grid (negative), smem staging + barrier (negative).
__global__ __launch_bounds__(128, 8)
void hash_ngram_kernel(const int* __restrict__ tokens,
                       const float* __restrict__ main_w,
                       const float* __restrict__ shared_w,
                       const float* __restrict__ size_w,
                       float* __restrict__ out)
{
    const int pos  = blockIdx.x * 2 + (threadIdx.x >> 6);  // warp-uniform
    const int d8   = threadIdx.x & 63;                     // 32B lane
    const int b    = pos >> 13;            // / SEQ_LEN
    const int s    = pos & (SEQ_LEN - 1);  // % SEQ_LEN
    const int base = b * SEQ_LEN + s;

    // Hash chain over the 8 trailing tokens (redundant per thread; token
    // loads are warp-uniform broadcasts, L1-hot).
    int sidx[MAX_N - 2];
    int tok0;
    {
        unsigned P   = 1u;   // 260^j mod 2^23
        unsigned acc = 0u;   // running sum of masked terms
        #pragma unroll
        for (int j = 0; j < MAX_N; ++j) {
            const int t = (s - j >= 0) ? __ldg(&tokens[base - j]) : 0;
            if (j == 0) tok0 = t;
            acc += ((unsigned)t * P) & HASH_MASK;    // t[s-j]*260^j mod 2^23
            P = (P * HASH_BASE) & HASH_MASK;
            const int n = j + 1;                     // n-gram length
            if (n >= 3) {
                const unsigned h = acc & HASH_MASK;  // sum mod 2^23
                sidx[n - 3] = (s >= n - 1) ? (int)(h % NBUCKETS) : 0;
            }
        }
    }

    const int doff = d8 * 8;  // float offset within the 512-dim row

    // 6 DRAM gathers FIRST (256-bit each), batched for MLP.
    F8 vg[MAX_N - 2];
    #pragma unroll
    for (int r = 0; r < MAX_N - 2; ++r)
        vg[r] = ldg256_el(shared_w + (size_t)sidx[r] * EMBED_DIM + doff);

    // Cached work under the DRAM flight: main row (L2-resident) seeds the
    // accumulator, then the 6 L1-resident size_w rows fold in.
    float a[8];
    {
        F8 vm = ldg256(main_w + (size_t)tok0 * EMBED_DIM + doff);
        #pragma unroll
        for (int k = 0; k < 8; ++k) a[k] = vm.v[k];
        #pragma unroll
        for (int r = 0; r < MAX_N - 2; ++r) {
            F8 vz = ldg256(size_w + (size_t)r * EMBED_DIM + doff);
            #pragma unroll
            for (int k = 0; k < 8; ++k) a[k] += vz.v[k];
        }
    }

    // Consume the gathers.
    #pragma unroll
    for (int r = 0; r < MAX_N - 2; ++r)
        #pragma unroll
        for (int k = 0; k < 8; ++k) a[k] += vg[r].v[k];

    const float inv = 1.0f / 7.0f;   // 1 + (MAX_N - 2) contributors
    float4 o0, o1;
    o0.x = a[0]*inv; o0.y = a[1]*inv; o0.z = a[2]*inv; o0.w = a[3]*inv;
    o1.x = a[4]*inv; o1.y = a[5]*inv; o1.z = a[6]*inv; o1.w = a[7]*inv;

    // Streaming stores: keep the 64MB output from evicting gather lines.
    float4* o4 = (float4*)(out + (size_t)pos * EMBED_DIM + doff);
    __stcs(&o4[0], o0);
    __stcs(&o4[1], o1);
}

extern "C" void kernel_launch(void* const* d_in, const int* in_sizes, int n_in,
                              void* d_out, int out_size)
{
    const int*   tokens   = (const int*)  d_in[0];   // [4, 8192] int32
    const float* main_w   = (const float*)d_in[1];   // [259, 512] f32
    const float* shared_w = (const float*)d_in[2];   // [500000, 512] f32
    const float* size_w   = (const float*)d_in[3];   // [6, 512] f32
    float*       out      = (float*)d_out;           // [4, 8192, 512] f32

    (void)in_sizes; (void)n_in; (void)out_size;

    hash_ngram_kernel<<<NPOS / 2, 128>>>(tokens, main_w, shared_w, size_w, out);
}